// round 3
// baseline (speedup 1.0000x reference)
#include <cuda_runtime.h>

#define BS 2
#define NN 2048
#define DIN 128
#define DOUT 128
#define H 8
#define DK 16

// -------- scratch (no allocs allowed) --------
__device__ float g_Q[(size_t)BS*H*NN*DK];
__device__ float g_K[(size_t)BS*H*NN*DK];
__device__ float g_V[(size_t)BS*H*NN*DK];
__device__ float g_stat[(size_t)BS*H*NN*2];   // per row: max, inv_sum

// ============================================================
// Projection: y = X @ W^T + b, written as [b][h][n][dk]
// grid (4096/64, 3), block 256
// ============================================================
#define PBM 64
__global__ __launch_bounds__(256) void proj_kernel(
    const float* __restrict__ X,
    const float* __restrict__ Wq, const float* __restrict__ bq,
    const float* __restrict__ Wk, const float* __restrict__ bk,
    const float* __restrict__ Wv, const float* __restrict__ bv)
{
    __shared__ float Xs[PBM][33];
    __shared__ float Wt[32][128];

    int tid = threadIdx.x;
    int sel = blockIdx.y;
    const float* W    = (sel == 0) ? Wq : ((sel == 1) ? Wk : Wv);
    const float* bias = (sel == 0) ? bq : ((sel == 1) ? bk : bv);
    float* dst        = (sel == 0) ? g_Q : ((sel == 1) ? g_K : g_V);

    int tx = tid & 63;
    int ty = tid >> 6;
    int row0 = blockIdx.x * PBM;

    float acc0[16], acc1[16];
#pragma unroll
    for (int i = 0; i < 16; i++) { acc0[i] = 0.f; acc1[i] = 0.f; }

    for (int k0 = 0; k0 < DIN; k0 += 32) {
        __syncthreads();
#pragma unroll
        for (int r = 0; r < 2; r++) {
            int i = tid + 256 * r;
            int xr = i >> 3;
            int xc = (i & 7) << 2;
            float4 xv = *(const float4*)(X + (size_t)(row0 + xr) * DIN + k0 + xc);
            Xs[xr][xc + 0] = xv.x; Xs[xr][xc + 1] = xv.y;
            Xs[xr][xc + 2] = xv.z; Xs[xr][xc + 3] = xv.w;
        }
#pragma unroll
        for (int r = 0; r < 4; r++) {
            int i = tid + 256 * r;
            int o  = i >> 3;
            int kc = (i & 7) << 2;
            float4 wv = *(const float4*)(W + (size_t)o * DIN + k0 + kc);
            Wt[kc + 0][o] = wv.x; Wt[kc + 1][o] = wv.y;
            Wt[kc + 2][o] = wv.z; Wt[kc + 3][o] = wv.w;
        }
        __syncthreads();
#pragma unroll
        for (int kk = 0; kk < 32; kk++) {
            float w0 = Wt[kk][tx];
            float w1 = Wt[kk][tx + 64];
#pragma unroll
            for (int rr = 0; rr < 16; rr++) {
                float xv = Xs[ty * 16 + rr][kk];
                acc0[rr] = fmaf(xv, w0, acc0[rr]);
                acc1[rr] = fmaf(xv, w1, acc1[rr]);
            }
        }
    }

    float b0 = bias[tx], b1 = bias[tx + 64];
    int c0 = tx, c1 = tx + 64;
#pragma unroll
    for (int rr = 0; rr < 16; rr++) {
        int grow = row0 + ty * 16 + rr;
        int b = grow / NN, n = grow % NN;
        dst[(((size_t)b * H + (c0 >> 4)) * NN + n) * DK + (c0 & 15)] = acc0[rr] + b0;
        dst[(((size_t)b * H + (c1 >> 4)) * NN + n) * DK + (c1 & 15)] = acc1[rr] + b1;
    }
}

// ============================================================
// Kernel 1: scores -> attnp (raw), online max/sum -> g_stat
// warp = 4 query rows; block = 8 warps = 32 rows
// grid (2048/32, 8, 2)
// ============================================================
#define TM 512
#define ROWS_PER_WARP 4
#define ROWS_PER_BLK 32
#define SJ (TM / 32)

__global__ __launch_bounds__(256, 2) void score_kernel(
    const float* __restrict__ sp, const int* __restrict__ adj,
    float* __restrict__ scorep)
{
    __shared__ float ts[TM * 20];

    int tid = threadIdx.x;
    int w = tid >> 5;
    int l = tid & 31;
    int h = blockIdx.y, b = blockIdx.z;
    int n0 = blockIdx.x * ROWS_PER_BLK + w * ROWS_PER_WARP;
    int bh = b * H + h;

    const float* kb = g_K + (size_t)bh * NN * DK;

    // q pre-scaled by 0.25
    float q[ROWS_PER_WARP][DK];
#pragma unroll
    for (int r = 0; r < ROWS_PER_WARP; r++) {
        const float* qr = g_Q + ((size_t)bh * NN + n0 + r) * DK;
#pragma unroll
        for (int d4 = 0; d4 < 4; d4++) {
            float4 t = *(const float4*)(qr + d4 * 4);
            q[r][d4*4+0] = t.x*0.25f; q[r][d4*4+1] = t.y*0.25f;
            q[r][d4*4+2] = t.z*0.25f; q[r][d4*4+3] = t.w*0.25f;
        }
    }

    float mx[ROWS_PER_WARP], S[ROWS_PER_WARP];
#pragma unroll
    for (int r = 0; r < ROWS_PER_WARP; r++) { mx[r] = -3.0e38f; S[r] = 0.f; }

    for (int t = 0; t < NN / TM; t++) {
        __syncthreads();
#pragma unroll
        for (int rr = 0; rr < 8; rr++) {
            int i  = tid + 256 * rr;
            int mi = i >> 2;
            int d4 = (i & 3) << 2;
            float4 kv = *(const float4*)(kb + ((size_t)(t * TM + mi)) * DK + d4);
            *(float4*)(ts + mi * 20 + d4) = kv;
        }
        __syncthreads();

#pragma unroll
        for (int jj = 0; jj < SJ; jj++) {
            int lm = (jj << 5) + l;
            int m  = t * TM + lm;
            const float4* kr = (const float4*)(ts + lm * 20);
            float4 k0 = kr[0], k1 = kr[1], k2 = kr[2], k3 = kr[3];

#pragma unroll
            for (int r = 0; r < ROWS_PER_WARP; r++) {
                int n = n0 + r;
                float a0 = q[r][0]*k0.x;   a0 = fmaf(q[r][1],k0.y,a0);
                a0 = fmaf(q[r][2],k0.z,a0); a0 = fmaf(q[r][3],k0.w,a0);
                float a1 = q[r][4]*k1.x;   a1 = fmaf(q[r][5],k1.y,a1);
                a1 = fmaf(q[r][6],k1.z,a1); a1 = fmaf(q[r][7],k1.w,a1);
                float a2 = q[r][8]*k2.x;   a2 = fmaf(q[r][9],k2.y,a2);
                a2 = fmaf(q[r][10],k2.z,a2); a2 = fmaf(q[r][11],k2.w,a2);
                float a3 = q[r][12]*k3.x;  a3 = fmaf(q[r][13],k3.y,a3);
                a3 = fmaf(q[r][14],k3.z,a3); a3 = fmaf(q[r][15],k3.w,a3);
                float dot = (a0 + a1) + (a2 + a3);

                float sv = sp[(size_t)n * NN + m];
                if (m == n) sv = 0.f;
                int msk = adj[((size_t)b * NN + n) * NN + m];
                float sval = msk ? (dot + sv) : -1e10f;

                scorep[((size_t)bh * NN + n) * NN + m] = sval;

                if (sval > mx[r]) {
                    S[r] = S[r] * __expf(mx[r] - sval) + 1.0f;
                    mx[r] = sval;
                } else {
                    S[r] += __expf(sval - mx[r]);
                }
            }
        }
    }

    // warp-reduce (max, sum) exactly
#pragma unroll
    for (int r = 0; r < ROWS_PER_WARP; r++) {
        float m_r = mx[r], s_r = S[r];
#pragma unroll
        for (int off = 16; off; off >>= 1) {
            float mo = __shfl_xor_sync(0xffffffffu, m_r, off);
            float so = __shfl_xor_sync(0xffffffffu, s_r, off);
            float mn = fmaxf(m_r, mo);
            s_r = s_r * __expf(m_r - mn) + so * __expf(mo - mn);
            m_r = mn;
        }
        if (l == 0) {
            size_t row = (size_t)bh * NN + n0 + r;
            g_stat[row * 2 + 0] = m_r;
            g_stat[row * 2 + 1] = 1.0f / s_r;
        }
    }
}

// ============================================================
// Kernel 2: read raw scores, write p in place, PV accumulate
// warp = 4 query rows; block = 8 warps = 32 rows
// ============================================================
__global__ __launch_bounds__(256, 2) void pv_kernel(
    float* __restrict__ scorep, float* __restrict__ outp)
{
    __shared__ float ts[TM * 20];

    int tid = threadIdx.x;
    int w = tid >> 5;
    int l = tid & 31;
    int h = blockIdx.y, b = blockIdx.z;
    int n0 = blockIdx.x * ROWS_PER_BLK + w * ROWS_PER_WARP;
    int bh = b * H + h;

    const float* vb = g_V + (size_t)bh * NN * DK;

    float mx[ROWS_PER_WARP], inv[ROWS_PER_WARP];
#pragma unroll
    for (int r = 0; r < ROWS_PER_WARP; r++) {
        size_t row = (size_t)bh * NN + n0 + r;
        mx[r]  = g_stat[row * 2 + 0];
        inv[r] = g_stat[row * 2 + 1];
    }

    float o[ROWS_PER_WARP][DK];
#pragma unroll
    for (int r = 0; r < ROWS_PER_WARP; r++)
#pragma unroll
        for (int d = 0; d < DK; d++) o[r][d] = 0.f;

    for (int t = 0; t < NN / TM; t++) {
        __syncthreads();
#pragma unroll
        for (int rr = 0; rr < 8; rr++) {
            int i  = tid + 256 * rr;
            int mi = i >> 2;
            int d4 = (i & 3) << 2;
            float4 vv = *(const float4*)(vb + ((size_t)(t * TM + mi)) * DK + d4);
            *(float4*)(ts + mi * 20 + d4) = vv;
        }
        __syncthreads();

#pragma unroll
        for (int jj = 0; jj < SJ; jj++) {
            int lm = (jj << 5) + l;
            int m  = t * TM + lm;
            const float4* vr = (const float4*)(ts + lm * 20);
            float4 v0 = vr[0], v1 = vr[1], v2 = vr[2], v3 = vr[3];

#pragma unroll
            for (int r = 0; r < ROWS_PER_WARP; r++) {
                size_t idx = ((size_t)bh * NN + n0 + r) * NN + m;
                float sraw = scorep[idx];
                float p = __expf(sraw - mx[r]) * inv[r];
                scorep[idx] = p;
                o[r][0]  = fmaf(p, v0.x, o[r][0]);  o[r][1]  = fmaf(p, v0.y, o[r][1]);
                o[r][2]  = fmaf(p, v0.z, o[r][2]);  o[r][3]  = fmaf(p, v0.w, o[r][3]);
                o[r][4]  = fmaf(p, v1.x, o[r][4]);  o[r][5]  = fmaf(p, v1.y, o[r][5]);
                o[r][6]  = fmaf(p, v1.z, o[r][6]);  o[r][7]  = fmaf(p, v1.w, o[r][7]);
                o[r][8]  = fmaf(p, v2.x, o[r][8]);  o[r][9]  = fmaf(p, v2.y, o[r][9]);
                o[r][10] = fmaf(p, v2.z, o[r][10]); o[r][11] = fmaf(p, v2.w, o[r][11]);
                o[r][12] = fmaf(p, v3.x, o[r][12]); o[r][13] = fmaf(p, v3.y, o[r][13]);
                o[r][14] = fmaf(p, v3.z, o[r][14]); o[r][15] = fmaf(p, v3.w, o[r][15]);
            }
        }
    }

    // butterfly reduce all rows' partials
#pragma unroll
    for (int off = 16; off; off >>= 1) {
#pragma unroll
        for (int r = 0; r < ROWS_PER_WARP; r++)
#pragma unroll
            for (int d = 0; d < DK; d++)
                o[r][d] += __shfl_xor_sync(0xffffffffu, o[r][d], off);
    }

    // out layout: out[(b*N+n)*128 + d*8 + h]; lane r writes row n0+r
    if (outp && l < ROWS_PER_WARP) {
        int n = n0 + l;
        float* ob = outp + ((size_t)b * NN + n) * DOUT + h;
#pragma unroll
        for (int d = 0; d < DK; d++) ob[(size_t)d * H] = o[l][d];
    }
}

// ============================================================
extern "C" void kernel_launch(void* const* d_in, const int* in_sizes, int n_in,
                              void* d_out, int out_size) {
    const float* x   = (const float*)d_in[0];
    const int*   adj = (const int*)  d_in[1];
    const float* sp  = (const float*)d_in[2];
    const float* Wq  = (const float*)d_in[3];
    const float* bq  = (const float*)d_in[4];
    const float* Wk  = (const float*)d_in[5];
    const float* bk  = (const float*)d_in[6];
    const float* Wv  = (const float*)d_in[7];
    const float* bv  = (const float*)d_in[8];

    const long long OUT_ELEMS  = (long long)BS * NN * DOUT;              // 524288
    const long long ATTN_ELEMS = (long long)BS * H * NN * (long long)NN; // 67108864

    float* base  = (float*)d_out;
    float* outp  = nullptr;
    float* attnp = nullptr;
    long long osz = (long long)out_size;
    if (osz >= OUT_ELEMS + ATTN_ELEMS) { outp = base; attnp = base + OUT_ELEMS; }
    else if (osz == ATTN_ELEMS)        { attnp = base; }
    else                               { outp = base; }

    float* scorep = attnp ? attnp : base;   // attn buffer doubles as score scratch

    dim3 pgrid(BS * NN / PBM, 3);
    proj_kernel<<<pgrid, 256>>>(x, Wq, bq, Wk, bk, Wv, bv);

    dim3 agrid(NN / ROWS_PER_BLK, H, BS);
    score_kernel<<<agrid, 256>>>(sp, adj, scorep);
    pv_kernel<<<agrid, 256>>>(scorep, outp);
}

// round 4
// speedup vs baseline: 2.3341x; 2.3341x over previous
#include <cuda_runtime.h>

typedef unsigned long long ull;

#define BS 2
#define NN 2048
#define DIN 128
#define DOUT 128
#define H 8
#define DK 16

#define TM 256
#define NT (NN / TM)      // 8 tiles
#define STRD (TM + 4)     // 260 floats, 16B-aligned rows, conflict-free

// -------- scratch (no allocs allowed) --------
__device__ float g_Q[(size_t)BS*H*NN*DK];
__device__ float g_K[(size_t)BS*H*NN*DK];
__device__ float g_V[(size_t)BS*H*NN*DK];

// ---------- f32x2 helpers ----------
__device__ __forceinline__ void ffma2(ull& d, ull a, ull b) {
    asm("fma.rn.f32x2 %0, %1, %2, %0;" : "+l"(d) : "l"(a), "l"(b));
}
__device__ __forceinline__ ull pk2(float a, float b) {
    ull r; asm("mov.b64 %0, {%1, %2};" : "=l"(r) : "f"(a), "f"(b)); return r;
}
__device__ __forceinline__ float2 upk(ull v) {
    float2 r; asm("mov.b64 {%0, %1}, %2;" : "=f"(r.x), "=f"(r.y) : "l"(v)); return r;
}

// ============================================================
// Projection: y = X @ W^T + b, written as [b][h][n][dk]
// ============================================================
#define PBM 64
__global__ __launch_bounds__(256, 2) void proj_kernel(
    const float* __restrict__ X,
    const float* __restrict__ Wq, const float* __restrict__ bq,
    const float* __restrict__ Wk, const float* __restrict__ bk,
    const float* __restrict__ Wv, const float* __restrict__ bv)
{
    __shared__ float Xs[PBM][33];
    __shared__ float Wt[32][128];

    int tid = threadIdx.x;
    int sel = blockIdx.y;
    const float* W    = (sel == 0) ? Wq : ((sel == 1) ? Wk : Wv);
    const float* bias = (sel == 0) ? bq : ((sel == 1) ? bk : bv);
    float* dst        = (sel == 0) ? g_Q : ((sel == 1) ? g_K : g_V);

    int tx = tid & 63;
    int ty = tid >> 6;
    int row0 = blockIdx.x * PBM;

    float acc0[16], acc1[16];
#pragma unroll
    for (int i = 0; i < 16; i++) { acc0[i] = 0.f; acc1[i] = 0.f; }

    for (int k0 = 0; k0 < DIN; k0 += 32) {
        __syncthreads();
#pragma unroll
        for (int r = 0; r < 2; r++) {
            int i = tid + 256 * r;
            int xr = i >> 3;
            int xc = (i & 7) << 2;
            float4 xv = *(const float4*)(X + (size_t)(row0 + xr) * DIN + k0 + xc);
            Xs[xr][xc + 0] = xv.x; Xs[xr][xc + 1] = xv.y;
            Xs[xr][xc + 2] = xv.z; Xs[xr][xc + 3] = xv.w;
        }
#pragma unroll
        for (int r = 0; r < 4; r++) {
            int i = tid + 256 * r;
            int o  = i >> 3;
            int kc = (i & 7) << 2;
            float4 wv = *(const float4*)(W + (size_t)o * DIN + k0 + kc);
            Wt[kc + 0][o] = wv.x; Wt[kc + 1][o] = wv.y;
            Wt[kc + 2][o] = wv.z; Wt[kc + 3][o] = wv.w;
        }
        __syncthreads();
#pragma unroll
        for (int kk = 0; kk < 32; kk++) {
            float w0 = Wt[kk][tx];
            float w1 = Wt[kk][tx + 64];
#pragma unroll
            for (int rr = 0; rr < 16; rr++) {
                float xv = Xs[ty * 16 + rr][kk];
                acc0[rr] = fmaf(xv, w0, acc0[rr]);
                acc1[rr] = fmaf(xv, w1, acc1[rr]);
            }
        }
    }

    float b0 = bias[tx], b1 = bias[tx + 64];
    int c0 = tx, c1 = tx + 64;
#pragma unroll
    for (int rr = 0; rr < 16; rr++) {
        int grow = row0 + ty * 16 + rr;
        int b = grow / NN, n = grow % NN;
        dst[(((size_t)b * H + (c0 >> 4)) * NN + n) * DK + (c0 & 15)] = acc0[rr] + b0;
        dst[(((size_t)b * H + (c1 >> 4)) * NN + n) * DK + (c1 & 15)] = acc1[rr] + b1;
    }
}

// ============================================================
// Fused attention: 8 warps x 2 rows = 16 rows/block, grid (128,8,2)
// Pass 1: QK (f32x2) -> online (max,sum). Pass 2: recompute QK,
// exp, STG.128 attn, PV from transposed V tile.
// Lane l owns m = base + 4l .. 4l+3 (all global traffic 16B vectorized).
// ============================================================
#define ROWS_PB 16

__global__ __launch_bounds__(256, 2) void attn_kernel(
    const float* __restrict__ sp, const int* __restrict__ adj,
    float* __restrict__ outp, float* __restrict__ attnp)
{
    __shared__ float tsK[DK][STRD];   // transposed: [d][m]
    __shared__ float tsV[DK][STRD];

    int tid = threadIdx.x;
    int w = tid >> 5;
    int l = tid & 31;
    int h = blockIdx.y, b = blockIdx.z;
    int bh = b * H + h;
    int n0 = blockIdx.x * ROWS_PB + w * 2;
    int n1 = n0 + 1;

    const float* kb = g_K + (size_t)bh * NN * DK;
    const float* vb = g_V + (size_t)bh * NN * DK;

    // q packs (q[d], q[d]) pre-scaled by 1/sqrt(DK)=0.25
    ull qq0[DK], qq1[DK];
    {
        const float* qr0 = g_Q + ((size_t)bh * NN + n0) * DK;
        const float* qr1 = g_Q + ((size_t)bh * NN + n1) * DK;
#pragma unroll
        for (int d = 0; d < DK; d++) {
            float v0 = qr0[d] * 0.25f;
            float v1 = qr1[d] * 0.25f;
            qq0[d] = pk2(v0, v0);
            qq1[d] = pk2(v1, v1);
        }
    }

    const float* sp0 = sp + (size_t)n0 * NN;
    const float* sp1 = sp + (size_t)n1 * NN;
    const int* ad0 = adj + ((size_t)b * NN + n0) * NN;
    const int* ad1 = adj + ((size_t)b * NN + n1) * NN;

    float mx0 = -3.0e38f, mx1 = -3.0e38f, S0 = 0.f, S1 = 0.f;

    // ================= Pass 1: stats =================
    for (int t = 0; t < NT; t++) {
        __syncthreads();
#pragma unroll
        for (int r = 0; r < 4; r++) {
            int f = tid + 256 * r;            // 0..1023 float4s
            int m = f >> 2;
            int dg = (f & 3) << 2;
            float4 kv = *(const float4*)(kb + ((size_t)(t * TM + m)) * DK + dg);
            tsK[dg + 0][m] = kv.x; tsK[dg + 1][m] = kv.y;
            tsK[dg + 2][m] = kv.z; tsK[dg + 3][m] = kv.w;
        }
        __syncthreads();

#pragma unroll
        for (int c = 0; c < 2; c++) {
            int mm = c * 128 + 4 * l;       // within tile
            int mg = t * TM + mm;           // global m

            ull d0a = 0ull, d0b = 0ull, d1a = 0ull, d1b = 0ull;
#pragma unroll
            for (int d = 0; d < DK; d++) {
                ulonglong2 kk = *(const ulonglong2*)&tsK[d][mm];
                ffma2(d0a, qq0[d], kk.x); ffma2(d0b, qq0[d], kk.y);
                ffma2(d1a, qq1[d], kk.x); ffma2(d1b, qq1[d], kk.y);
            }
            float2 u0a = upk(d0a), u0b = upk(d0b), u1a = upk(d1a), u1b = upk(d1b);

            float4 sv0 = *(const float4*)(sp0 + mg);
            float4 sv1 = *(const float4*)(sp1 + mg);
            int4 a0 = *(const int4*)(ad0 + mg);
            int4 a1 = *(const int4*)(ad1 + mg);

            sv0.x = (mg + 0 == n0) ? 0.f : sv0.x;
            sv0.y = (mg + 1 == n0) ? 0.f : sv0.y;
            sv0.z = (mg + 2 == n0) ? 0.f : sv0.z;
            sv0.w = (mg + 3 == n0) ? 0.f : sv0.w;
            sv1.x = (mg + 0 == n1) ? 0.f : sv1.x;
            sv1.y = (mg + 1 == n1) ? 0.f : sv1.y;
            sv1.z = (mg + 2 == n1) ? 0.f : sv1.z;
            sv1.w = (mg + 3 == n1) ? 0.f : sv1.w;

            float s00 = a0.x ? (u0a.x + sv0.x) : -1e10f;
            float s01 = a0.y ? (u0a.y + sv0.y) : -1e10f;
            float s02 = a0.z ? (u0b.x + sv0.z) : -1e10f;
            float s03 = a0.w ? (u0b.y + sv0.w) : -1e10f;
            float s10 = a1.x ? (u1a.x + sv1.x) : -1e10f;
            float s11 = a1.y ? (u1a.y + sv1.y) : -1e10f;
            float s12 = a1.z ? (u1b.x + sv1.z) : -1e10f;
            float s13 = a1.w ? (u1b.y + sv1.w) : -1e10f;

            float cm0 = fmaxf(fmaxf(s00, s01), fmaxf(s02, s03));
            float nm0 = fmaxf(mx0, cm0);
            S0 = S0 * __expf(mx0 - nm0)
               + __expf(s00 - nm0) + __expf(s01 - nm0)
               + __expf(s02 - nm0) + __expf(s03 - nm0);
            mx0 = nm0;

            float cm1 = fmaxf(fmaxf(s10, s11), fmaxf(s12, s13));
            float nm1 = fmaxf(mx1, cm1);
            S1 = S1 * __expf(mx1 - nm1)
               + __expf(s10 - nm1) + __expf(s11 - nm1)
               + __expf(s12 - nm1) + __expf(s13 - nm1);
            mx1 = nm1;
        }
    }

    // warp-combine (max,sum) exactly; all lanes end with result
#pragma unroll
    for (int off = 16; off; off >>= 1) {
        float mo = __shfl_xor_sync(0xffffffffu, mx0, off);
        float so = __shfl_xor_sync(0xffffffffu, S0, off);
        float nm = fmaxf(mx0, mo);
        S0 = S0 * __expf(mx0 - nm) + so * __expf(mo - nm);
        mx0 = nm;
        mo = __shfl_xor_sync(0xffffffffu, mx1, off);
        so = __shfl_xor_sync(0xffffffffu, S1, off);
        nm = fmaxf(mx1, mo);
        S1 = S1 * __expf(mx1 - nm) + so * __expf(mo - nm);
        mx1 = nm;
    }
    float inv0 = 1.f / S0, inv1 = 1.f / S1;

    // ================= Pass 2: p-write + PV =================
    float o0[DK], o1[DK];
#pragma unroll
    for (int d = 0; d < DK; d++) { o0[d] = 0.f; o1[d] = 0.f; }
    size_t ar0 = ((size_t)bh * NN + n0) * NN;
    size_t ar1 = ((size_t)bh * NN + n1) * NN;

    for (int t = 0; t < NT; t++) {
        __syncthreads();
#pragma unroll
        for (int r = 0; r < 4; r++) {
            int f = tid + 256 * r;
            int m = f >> 2;
            int dg = (f & 3) << 2;
            float4 kv = *(const float4*)(kb + ((size_t)(t * TM + m)) * DK + dg);
            tsK[dg + 0][m] = kv.x; tsK[dg + 1][m] = kv.y;
            tsK[dg + 2][m] = kv.z; tsK[dg + 3][m] = kv.w;
            float4 vv = *(const float4*)(vb + ((size_t)(t * TM + m)) * DK + dg);
            tsV[dg + 0][m] = vv.x; tsV[dg + 1][m] = vv.y;
            tsV[dg + 2][m] = vv.z; tsV[dg + 3][m] = vv.w;
        }
        __syncthreads();

#pragma unroll
        for (int c = 0; c < 2; c++) {
            int mm = c * 128 + 4 * l;
            int mg = t * TM + mm;

            ull d0a = 0ull, d0b = 0ull, d1a = 0ull, d1b = 0ull;
#pragma unroll
            for (int d = 0; d < DK; d++) {
                ulonglong2 kk = *(const ulonglong2*)&tsK[d][mm];
                ffma2(d0a, qq0[d], kk.x); ffma2(d0b, qq0[d], kk.y);
                ffma2(d1a, qq1[d], kk.x); ffma2(d1b, qq1[d], kk.y);
            }
            float2 u0a = upk(d0a), u0b = upk(d0b), u1a = upk(d1a), u1b = upk(d1b);

            float4 sv0 = *(const float4*)(sp0 + mg);
            float4 sv1 = *(const float4*)(sp1 + mg);
            int4 a0 = *(const int4*)(ad0 + mg);
            int4 a1 = *(const int4*)(ad1 + mg);

            sv0.x = (mg + 0 == n0) ? 0.f : sv0.x;
            sv0.y = (mg + 1 == n0) ? 0.f : sv0.y;
            sv0.z = (mg + 2 == n0) ? 0.f : sv0.z;
            sv0.w = (mg + 3 == n0) ? 0.f : sv0.w;
            sv1.x = (mg + 0 == n1) ? 0.f : sv1.x;
            sv1.y = (mg + 1 == n1) ? 0.f : sv1.y;
            sv1.z = (mg + 2 == n1) ? 0.f : sv1.z;
            sv1.w = (mg + 3 == n1) ? 0.f : sv1.w;

            float s00 = a0.x ? (u0a.x + sv0.x) : -1e10f;
            float s01 = a0.y ? (u0a.y + sv0.y) : -1e10f;
            float s02 = a0.z ? (u0b.x + sv0.z) : -1e10f;
            float s03 = a0.w ? (u0b.y + sv0.w) : -1e10f;
            float s10 = a1.x ? (u1a.x + sv1.x) : -1e10f;
            float s11 = a1.y ? (u1a.y + sv1.y) : -1e10f;
            float s12 = a1.z ? (u1b.x + sv1.z) : -1e10f;
            float s13 = a1.w ? (u1b.y + sv1.w) : -1e10f;

            float p00 = __expf(s00 - mx0) * inv0;
            float p01 = __expf(s01 - mx0) * inv0;
            float p02 = __expf(s02 - mx0) * inv0;
            float p03 = __expf(s03 - mx0) * inv0;
            float p10 = __expf(s10 - mx1) * inv1;
            float p11 = __expf(s11 - mx1) * inv1;
            float p12 = __expf(s12 - mx1) * inv1;
            float p13 = __expf(s13 - mx1) * inv1;

            if (attnp) {
                *(float4*)(attnp + ar0 + mg) = make_float4(p00, p01, p02, p03);
                *(float4*)(attnp + ar1 + mg) = make_float4(p10, p11, p12, p13);
            }

#pragma unroll
            for (int d = 0; d < DK; d++) {
                float4 vv = *(const float4*)&tsV[d][mm];
                o0[d] = fmaf(p00, vv.x, fmaf(p01, vv.y, fmaf(p02, vv.z, fmaf(p03, vv.w, o0[d]))));
                o1[d] = fmaf(p10, vv.x, fmaf(p11, vv.y, fmaf(p12, vv.z, fmaf(p13, vv.w, o1[d]))));
            }
        }
    }

    // butterfly reduce PV partials across lanes
#pragma unroll
    for (int off = 16; off; off >>= 1) {
#pragma unroll
        for (int d = 0; d < DK; d++) {
            o0[d] += __shfl_xor_sync(0xffffffffu, o0[d], off);
            o1[d] += __shfl_xor_sync(0xffffffffu, o1[d], off);
        }
    }

    // out layout: out[(b*N+n)*128 + d*8 + h]
    if (outp) {
        if (l == 0) {
            float* ob = outp + ((size_t)b * NN + n0) * DOUT + h;
#pragma unroll
            for (int d = 0; d < DK; d++) ob[(size_t)d * H] = o0[d];
        } else if (l == 1) {
            float* ob = outp + ((size_t)b * NN + n1) * DOUT + h;
#pragma unroll
            for (int d = 0; d < DK; d++) ob[(size_t)d * H] = o1[d];
        }
    }
}

// ============================================================
extern "C" void kernel_launch(void* const* d_in, const int* in_sizes, int n_in,
                              void* d_out, int out_size) {
    const float* x   = (const float*)d_in[0];
    const int*   adj = (const int*)  d_in[1];
    const float* sp  = (const float*)d_in[2];
    const float* Wq  = (const float*)d_in[3];
    const float* bq  = (const float*)d_in[4];
    const float* Wk  = (const float*)d_in[5];
    const float* bk  = (const float*)d_in[6];
    const float* Wv  = (const float*)d_in[7];
    const float* bv  = (const float*)d_in[8];

    const long long OUT_ELEMS  = (long long)BS * NN * DOUT;              // 524288
    const long long ATTN_ELEMS = (long long)BS * H * NN * (long long)NN; // 67108864

    float* base  = (float*)d_out;
    float* outp  = nullptr;
    float* attnp = nullptr;
    long long osz = (long long)out_size;
    if (osz >= OUT_ELEMS + ATTN_ELEMS) { outp = base; attnp = base + OUT_ELEMS; }
    else if (osz == ATTN_ELEMS)        { attnp = base; }
    else                               { outp = base; }

    dim3 pgrid(BS * NN / PBM, 3);
    proj_kernel<<<pgrid, 256>>>(x, Wq, bq, Wk, bk, Wv, bv);

    dim3 agrid(NN / ROWS_PB, H, BS);
    attn_kernel<<<agrid, 256>>>(sp, adj, outp, attnp);
}